// round 11
// baseline (speedup 1.0000x reference)
#include <cuda_runtime.h>
#include <math.h>
#include <stdint.h>

// Problem constants
#define NB 2
#define LT 6400
#define ST 6400
#define CT 256
#define GW 80
#define BORDER 2
#define SQ 0.19764235f   // sqrt(1/(256*0.1))
#define THRESH 0.2f
#define NTIL 50          // 6400/128 tiles per dim
#define LCH 64           // l-chunks in conf pass
#define LPER (LT / LCH)  // 100
#define SBLK 4           // s-blocks in conf pass (ceil(6400/2048))

// ---------------- scratch ----------------
__device__ float g_sim[(size_t)NB * LT * ST];          // stores E = exp(sim)
__device__ float g_rowinv[NB * LT];
__device__ float g_colinv[NB * ST];
__device__ float g_crowmax[NB * LT];
__device__ float g_ccolmax[NB * ST];
__device__ float g_prs[(size_t)NB * LT * NTIL];        // row partial sums of E
__device__ float g_pcs[(size_t)NB * NTIL * ST];        // col partial sums of E
__device__ float g_pcm[(size_t)NB * LCH * ST];         // conf col-max partials
__device__ float g_crp[(size_t)NB * LT * SBLK];        // conf row-max partials
// tf32 operands in MMA-fragment order:
// A: [n][mtile 50][kslab 32][m16blk 8][lane 32][slot 4]
// B: [n][ntile 50][kslab 32][n8blk 16][lane 32][slot 2]
__device__ float g_fa[(size_t)NB * NTIL * 32 * 8 * 128];
__device__ float g_fb[(size_t)NB * NTIL * 32 * 16 * 64];

// ---------------- helpers ----------------
__device__ __forceinline__ uint32_t smem_u32(const void* p) {
    uint32_t a;
    asm("{ .reg .u64 t; cvta.to.shared.u64 t, %1; cvt.u32.u64 %0, t; }" : "=r"(a) : "l"(p));
    return a;
}
__device__ __forceinline__ void cpa16(uint32_t dst, const void* src) {
    asm volatile("cp.async.cg.shared.global [%0], [%1], 16;" :: "r"(dst), "l"(src));
}
#define CP_COMMIT() asm volatile("cp.async.commit_group;")
#define CP_WAIT1()  asm volatile("cp.async.wait_group 1;")
#define CP_WAIT0()  asm volatile("cp.async.wait_group 0;")

__device__ __forceinline__ void lds128(uint32_t* r, uint32_t addr) {
    asm volatile("ld.shared.v4.b32 {%0,%1,%2,%3}, [%4];"
        : "=r"(r[0]), "=r"(r[1]), "=r"(r[2]), "=r"(r[3]) : "r"(addr));
}
__device__ __forceinline__ void lds64(uint32_t* r, uint32_t addr) {
    asm volatile("ld.shared.v2.b32 {%0,%1}, [%2];"
        : "=r"(r[0]), "=r"(r[1]) : "r"(addr));
}
__device__ __forceinline__ void mma_tf32(float* d, const uint32_t* a, const uint32_t* b) {
    asm volatile(
        "mma.sync.aligned.m16n8k8.row.col.f32.tf32.tf32.f32 "
        "{%0,%1,%2,%3}, {%4,%5,%6,%7}, {%8,%9}, {%0,%1,%2,%3};"
        : "+f"(d[0]), "+f"(d[1]), "+f"(d[2]), "+f"(d[3])
        : "r"(a[0]), "r"(a[1]), "r"(a[2]), "r"(a[3]), "r"(b[0]), "r"(b[1]));
}
__device__ __forceinline__ float to_tf32(float v) {
    uint32_t r;
    asm("cvt.rna.tf32.f32 %0, %1;" : "=r"(r) : "f"(v));
    return __uint_as_float(r);
}

// ---------------- K0: fp32 -> scaled tf32 in fragment order ----------------
__global__ __launch_bounds__(256) void prep_kernel(const float4* __restrict__ x0,
                                                   const float4* __restrict__ x1) {
    const int i = blockIdx.x * 256 + threadIdx.x;
    const int half = NB * LT * CT / 4;
    if (i < half) {
        float4 v4 = x0[i];
        const int e = i * 4;
        const int n = e / (LT * CT);
        const int rem = e - n * (LT * CT);
        const int m = rem / CT;
        const int k = rem % CT;
        const int mt = m / 128, mloc = m % 128;
        const int m16b = mloc >> 4, r16 = mloc & 15;
        const int kslab = k >> 3;
        const int slot = ((k & 4) >> 1) + ((r16 >> 3) & 1);
        const int tb = (r16 & 7) << 2;
        float* base = g_fa + ((((size_t)(n * NTIL + mt) * 32 + kslab) * 8 + m16b) << 7);
        float v[4] = {v4.x, v4.y, v4.z, v4.w};
#pragma unroll
        for (int j = 0; j < 4; j++)
            base[(tb + j) * 4 + slot] = to_tf32(v[j] * SQ);
    } else {
        const int ib = i - half;
        float4 v4 = x1[ib];
        const int e = ib * 4;
        const int n = e / (ST * CT);
        const int rem = e - n * (ST * CT);
        const int srow = rem / CT;
        const int k = rem % CT;
        const int nt = srow / 128, nloc = srow % 128;
        const int n8b = nloc >> 3, r8 = nloc & 7;
        const int kslab = k >> 3;
        const int slot = (k & 4) >> 2;
        const int tb = r8 << 2;
        float* base = g_fb + ((((size_t)(n * NTIL + nt) * 32 + kslab) * 16 + n8b) << 6);
        float v[4] = {v4.x, v4.y, v4.z, v4.w};
#pragma unroll
        for (int j = 0; j < 4; j++)
            base[(tb + j) * 2 + slot] = to_tf32(v[j] * SQ);
    }
}

// ---------------- K1: tf32 MMA GEMM, E=exp(sim), fused sums + zero-fill ----------------
#define KCHUNKS 8               // k32 chunks
#define STG_B 32768             // 16KB A + 16KB B per stage
#define ESTR 132                // epilogue f32 tile stride
#define DSMEM_B 67584           // max(2*STG_B=65536, 128*ESTR*4=67584)

extern __shared__ char dsm[];

__global__ __launch_bounds__(256, 2) void gemm_mma_kernel(float* __restrict__ out,
                                                          int write_ms) {
    const int n = blockIdx.z;
    const int mt = blockIdx.y;
    const int nt = blockIdx.x;
    const int bm = mt * 128;
    const int bn = nt * 128;
    const int tid = threadIdx.x;
    const int wid = tid >> 5;
    const int lane = tid & 31;
    const uint32_t sb = smem_u32(dsm);

    const int wm = wid & 3;
    const int wn = wid >> 2;

    float acc[2][8][4];
#pragma unroll
    for (int mi = 0; mi < 2; mi++)
#pragma unroll
        for (int nj = 0; nj < 8; nj++)
#pragma unroll
            for (int q = 0; q < 4; q++) acc[mi][nj][q] = 0.0f;

    const float4* fa4 = (const float4*)g_fa + (size_t)(n * NTIL + mt) * 8192;
    const float4* fb4 = (const float4*)g_fb + (size_t)(n * NTIL + nt) * 8192;

    auto load_chunk = [&](int c, int s) {
        uint32_t dA = sb + s * STG_B + tid * 16;
        uint32_t dB = dA + 16384;
        const float4* pA = fa4 + c * 1024 + tid;
        const float4* pB = fb4 + c * 1024 + tid;
#pragma unroll
        for (int q = 0; q < 4; q++) {
            cpa16(dA + q * 4096, pA + q * 256);
            cpa16(dB + q * 4096, pB + q * 256);
        }
    };

    load_chunk(0, 0);
    CP_COMMIT();

    for (int c = 0; c < KCHUNKS; c++) {
        const int s = c & 1;
        if (c < KCHUNKS - 1) {
            load_chunk(c + 1, s ^ 1);
            CP_COMMIT();
            CP_WAIT1();
        } else {
            CP_WAIT0();
        }
        __syncthreads();

        const uint32_t sA = sb + s * STG_B;
        const uint32_t sB = sA + 16384;

#pragma unroll
        for (int s8 = 0; s8 < 4; s8++) {
            uint32_t a[2][4];
#pragma unroll
            for (int mi = 0; mi < 2; mi++)
                lds128(a[mi], sA + (uint32_t)(((s8 * 8 + wm * 2 + mi) << 9) + lane * 16));
#pragma unroll
            for (int nj = 0; nj < 8; nj++) {
                uint32_t b[2];
                lds64(b, sB + (uint32_t)(((s8 * 16 + wn * 8 + nj) << 8) + lane * 8));
                mma_tf32(acc[0][nj], a[0], b);
                mma_tf32(acc[1][nj], a[1], b);
            }
        }
        __syncthreads();
    }

    // zero-fill this block's mask+scores tiles (overlaps with epilogue latency)
    if (write_ms) {
        float* Mn = out + (size_t)NB * LT * ST + (size_t)n * LT * ST;
        float* Sn = out + 2 * (size_t)NB * LT * ST + (size_t)n * LT * ST;
        const float4 z = make_float4(0.f, 0.f, 0.f, 0.f);
#pragma unroll
        for (int i = 0; i < 16; i++) {
            int idx = i * 256 + tid;
            int row = idx >> 5;
            int q = idx & 31;
            size_t off = (size_t)(bm + row) * ST + bn + q * 4;
            *(float4*)(Mn + off) = z;
            *(float4*)(Sn + off) = z;
        }
    }

    float* et = (float*)dsm;
#pragma unroll
    for (int mi = 0; mi < 2; mi++) {
        const int r1 = wm * 32 + mi * 16 + (lane >> 2);
#pragma unroll
        for (int nj = 0; nj < 8; nj++) {
            const int cc = wn * 64 + nj * 8 + 2 * (lane & 3);
            et[r1 * ESTR + cc]           = __expf(acc[mi][nj][0]);
            et[r1 * ESTR + cc + 1]       = __expf(acc[mi][nj][1]);
            et[(r1 + 8) * ESTR + cc]     = __expf(acc[mi][nj][2]);
            et[(r1 + 8) * ESTR + cc + 1] = __expf(acc[mi][nj][3]);
        }
    }
    __syncthreads();

    float* Cn = g_sim + (size_t)n * LT * ST;
#pragma unroll
    for (int i = 0; i < 16; i++) {
        int idx = i * 256 + tid;
        int row = idx >> 5;
        int q = idx & 31;
        float4 v = *(float4*)(et + row * ESTR + q * 4);
        *(float4*)(Cn + (size_t)(bm + row) * ST + bn + q * 4) = v;
    }

    {
        int row = tid >> 1, h = tid & 1;
        float s = 0.0f;
        const float* p = et + row * ESTR + h * 64;
#pragma unroll 16
        for (int j = 0; j < 64; j++) s += p[j];
        s += __shfl_xor_sync(0xffffffffu, s, 1);
        if (h == 0) g_prs[(size_t)(n * LT + bm + row) * NTIL + nt] = s;
    }
    {
        int col = tid >> 1, h = tid & 1;
        float s = 0.0f;
        const float* p = et + (h * 64) * ESTR + col;
#pragma unroll 16
        for (int j = 0; j < 64; j++) s += p[j * ESTR];
        s += __shfl_xor_sync(0xffffffffu, s, 1);
        if (h == 0) g_pcs[((size_t)n * NTIL + mt) * ST + bn + col] = s;
    }
}

// ---------------- merged small reductions ----------------
__global__ __launch_bounds__(256) void sum_merge() {
    int i = blockIdx.x * 256 + threadIdx.x;
    if (i < NB * LT) {
        const float* p = g_prs + (size_t)i * NTIL;
        float s = 0.0f;
#pragma unroll 10
        for (int t = 0; t < NTIL; t++) s += p[t];
        g_rowinv[i] = 1.0f / s;
    } else if (i < NB * LT + NB * ST) {
        int k = i - NB * LT;
        int n = k / ST, s = k % ST;
        float sum = 0.0f;
#pragma unroll 10
        for (int t = 0; t < NTIL; t++) sum += g_pcs[((size_t)n * NTIL + t) * ST + s];
        g_colinv[k] = 1.0f / sum;
    }
}
__global__ __launch_bounds__(256) void max_merge() {
    int i = blockIdx.x * 256 + threadIdx.x;
    if (i < NB * LT) {
        const float* p = g_crp + (size_t)i * SBLK;
        float m = 0.0f;
#pragma unroll
        for (int t = 0; t < SBLK; t++) m = fmaxf(m, p[t]);
        g_crowmax[i] = m;
    } else if (i < NB * LT + NB * ST) {
        int k = i - NB * LT;
        int n = k / ST, s = k % ST;
        float m = 0.0f;
#pragma unroll 16
        for (int t = 0; t < LCH; t++) m = fmaxf(m, g_pcm[((size_t)(n * LCH + t)) * ST + s]);
        g_ccolmax[k] = m;
    }
}

// ---------------- conf pass: thread owns 8 cols (2 x float4), walks LPER rows ----------------
__global__ __launch_bounds__(256) void conf_kernel(float* __restrict__ out) {
    const int s0 = blockIdx.x * 2048 + threadIdx.x * 8;
    const int by = blockIdx.y, n = blockIdx.z;
    const int lane = threadIdx.x & 31, wid = threadIdx.x >> 5;
    const bool valid = (s0 < ST);

    __shared__ float ris[LPER];
    __shared__ float wmx[8][LPER];
    for (int i = threadIdx.x; i < LPER; i += 256)
        ris[i] = g_rowinv[n * LT + by * LPER + i];
    __syncthreads();

    float4 ci0 = make_float4(0.f, 0.f, 0.f, 0.f), ci1 = ci0;
    if (valid) {
        ci0 = *(const float4*)(g_colinv + n * ST + s0);
        ci1 = *(const float4*)(g_colinv + n * ST + s0 + 4);
    }

    const size_t base = (size_t)n * LT * ST + (size_t)(by * LPER) * ST + s0;
    const float* Eb = g_sim + base;
    float* Ob = out + base;

    float cm[8] = {0.f, 0.f, 0.f, 0.f, 0.f, 0.f, 0.f, 0.f};
    for (int i = 0; i < LPER; i++) {
        const float ri = ris[i];
        float w = 0.0f;
        if (valid) {
            float4 E0 = *(const float4*)(Eb + (size_t)i * ST);
            float4 E1 = *(const float4*)(Eb + (size_t)i * ST + 4);
            float4 c0, c1;
            c0.x = E0.x * E0.x * ri * ci0.x;
            c0.y = E0.y * E0.y * ri * ci0.y;
            c0.z = E0.z * E0.z * ri * ci0.z;
            c0.w = E0.w * E0.w * ri * ci0.w;
            c1.x = E1.x * E1.x * ri * ci1.x;
            c1.y = E1.y * E1.y * ri * ci1.y;
            c1.z = E1.z * E1.z * ri * ci1.z;
            c1.w = E1.w * E1.w * ri * ci1.w;
            *(float4*)(Ob + (size_t)i * ST) = c0;
            *(float4*)(Ob + (size_t)i * ST + 4) = c1;
            cm[0] = fmaxf(cm[0], c0.x); cm[1] = fmaxf(cm[1], c0.y);
            cm[2] = fmaxf(cm[2], c0.z); cm[3] = fmaxf(cm[3], c0.w);
            cm[4] = fmaxf(cm[4], c1.x); cm[5] = fmaxf(cm[5], c1.y);
            cm[6] = fmaxf(cm[6], c1.z); cm[7] = fmaxf(cm[7], c1.w);
            w = fmaxf(fmaxf(fmaxf(c0.x, c0.y), fmaxf(c0.z, c0.w)),
                      fmaxf(fmaxf(c1.x, c1.y), fmaxf(c1.z, c1.w)));
        }
#pragma unroll
        for (int o = 16; o > 0; o >>= 1) w = fmaxf(w, __shfl_xor_sync(0xffffffffu, w, o));
        if (lane == 0) wmx[wid][i] = w;
    }
    if (valid) {
        float* pm = g_pcm + ((size_t)(n * LCH + by)) * ST + s0;
        *(float4*)(pm)     = make_float4(cm[0], cm[1], cm[2], cm[3]);
        *(float4*)(pm + 4) = make_float4(cm[4], cm[5], cm[6], cm[7]);
    }
    __syncthreads();
    for (int i = threadIdx.x; i < LPER; i += 256) {
        float m = wmx[0][i];
#pragma unroll
        for (int w = 1; w < 8; w++) m = fmaxf(m, wmx[w][i]);
        g_crp[((size_t)n * LT + by * LPER + i) * SBLK + blockIdx.x] = m;
    }
}

// ---------------- scatter: one block per row; write sparse matches ----------------
__global__ __launch_bounds__(256) void scatter_kernel(float* __restrict__ out) {
    const int l = blockIdx.x;
    const int n = blockIdx.y;
    const float rm = g_crowmax[n * LT + l];
    if (!(rm > THRESH)) return;
    const int h0 = l / GW, w0 = l % GW;
    if (h0 < BORDER || h0 >= GW - BORDER || w0 < BORDER || w0 >= GW - BORDER) return;

    const float* crow = out + ((size_t)n * LT + l) * ST;
    float* mrow = out + (size_t)NB * LT * ST + ((size_t)n * LT + l) * ST;
    float* srow = out + 2 * (size_t)NB * LT * ST + ((size_t)n * LT + l) * ST;
    const float* ccm = g_ccolmax + n * ST;

    for (int s = threadIdx.x; s < ST; s += 256) {
        float c = crow[s];
        if (c == rm && c > THRESH && c == ccm[s]) {
            const int h1 = s / GW, w1 = s % GW;
            if (h1 >= BORDER && h1 < GW - BORDER && w1 >= BORDER && w1 < GW - BORDER) {
                mrow[s] = 1.0f;
                srow[s] = c;
            }
        }
    }
}

// ---------------- host ----------------
extern "C" void kernel_launch(void* const* d_in, const int* in_sizes, int n_in,
                              void* d_out, int out_size) {
    const float* x0 = (const float*)d_in[0];
    const float* x1 = (const float*)d_in[1];
    float* out = (float*)d_out;

    static int smem_set = 0;
    if (!smem_set) {
        cudaFuncSetAttribute(gemm_mma_kernel, cudaFuncAttributeMaxDynamicSharedMemorySize,
                             DSMEM_B);
        smem_set = 1;
    }

    const size_t tot = (size_t)NB * LT * ST;
    int write_ms = (out_size >= (long long)(3 * tot)) ? 1 : 0;

    prep_kernel<<<(2 * NB * LT * CT / 4) / 256, 256>>>((const float4*)x0, (const float4*)x1);

    gemm_mma_kernel<<<dim3(NTIL, NTIL, NB), 256, DSMEM_B>>>(out, write_ms);

    sum_merge<<<(NB * (LT + ST) + 255) / 256, 256>>>();

    conf_kernel<<<dim3(SBLK, LCH, NB), 256>>>(out);

    max_merge<<<(NB * (LT + ST) + 255) / 256, 256>>>();

    if (write_ms) {
        scatter_kernel<<<dim3(LT, NB), 256>>>(out);
    }
}

// round 14
// speedup vs baseline: 1.4719x; 1.4719x over previous
#include <cuda_runtime.h>
#include <math.h>
#include <stdint.h>

// Problem constants
#define NB 2
#define LT 6400
#define ST 6400
#define CT 256
#define GW 80
#define BORDER 2
#define SQ 0.19764235f   // sqrt(1/(256*0.1))
#define THRESH 0.2f
#define NTIL 50          // 6400/128 tiles per dim
#define LCH 64           // l-chunks in conf pass
#define LPER (LT / LCH)  // 100
#define SBLK 4           // s-blocks in conf pass (ceil(6400/2048))

// ---------------- scratch ----------------
__device__ float g_sim[(size_t)NB * LT * ST];          // stores E = exp(sim)
__device__ float g_rowinv[NB * LT];
__device__ float g_colinv[NB * ST];
__device__ float g_crowmax[NB * LT];
__device__ float g_ccolmax[NB * ST];
__device__ float g_prs[(size_t)NB * LT * NTIL];        // row partial sums of E
__device__ float g_pcs[(size_t)NB * NTIL * ST];        // col partial sums of E
__device__ float g_pcm[(size_t)NB * LCH * ST];         // conf col-max partials
__device__ float g_crp[(size_t)NB * LT * SBLK];        // conf row-max partials
// tf32 operands in MMA-fragment order:
// A: [n][mtile 50][kslab 32][m16blk 8][lane 32][slot 4]
// B: [n][ntile 50][kslab 32][n8blk 16][lane 32][slot 2]
__device__ float g_fa[(size_t)NB * NTIL * 32 * 8 * 128];
__device__ float g_fb[(size_t)NB * NTIL * 32 * 16 * 64];

// ---------------- helpers ----------------
__device__ __forceinline__ uint32_t smem_u32(const void* p) {
    uint32_t a;
    asm("{ .reg .u64 t; cvta.to.shared.u64 t, %1; cvt.u32.u64 %0, t; }" : "=r"(a) : "l"(p));
    return a;
}
__device__ __forceinline__ void cpa16(uint32_t dst, const void* src) {
    asm volatile("cp.async.cg.shared.global [%0], [%1], 16;" :: "r"(dst), "l"(src));
}
#define CP_COMMIT() asm volatile("cp.async.commit_group;")
#define CP_WAIT1()  asm volatile("cp.async.wait_group 1;")
#define CP_WAIT0()  asm volatile("cp.async.wait_group 0;")

__device__ __forceinline__ void lds128(uint32_t* r, uint32_t addr) {
    asm volatile("ld.shared.v4.b32 {%0,%1,%2,%3}, [%4];"
        : "=r"(r[0]), "=r"(r[1]), "=r"(r[2]), "=r"(r[3]) : "r"(addr));
}
__device__ __forceinline__ void lds64(uint32_t* r, uint32_t addr) {
    asm volatile("ld.shared.v2.b32 {%0,%1}, [%2];"
        : "=r"(r[0]), "=r"(r[1]) : "r"(addr));
}
__device__ __forceinline__ void mma_tf32(float* d, const uint32_t* a, const uint32_t* b) {
    asm volatile(
        "mma.sync.aligned.m16n8k8.row.col.f32.tf32.tf32.f32 "
        "{%0,%1,%2,%3}, {%4,%5,%6,%7}, {%8,%9}, {%0,%1,%2,%3};"
        : "+f"(d[0]), "+f"(d[1]), "+f"(d[2]), "+f"(d[3])
        : "r"(a[0]), "r"(a[1]), "r"(a[2]), "r"(a[3]), "r"(b[0]), "r"(b[1]));
}
__device__ __forceinline__ float to_tf32(float v) {
    uint32_t r;
    asm("cvt.rna.tf32.f32 %0, %1;" : "=r"(r) : "f"(v));
    return __uint_as_float(r);
}

// ---------------- K0: fp32 -> scaled tf32 in fragment order ----------------
__global__ __launch_bounds__(256) void prep_kernel(const float4* __restrict__ x0,
                                                   const float4* __restrict__ x1) {
    const int i = blockIdx.x * 256 + threadIdx.x;
    const int half = NB * LT * CT / 4;
    if (i < half) {
        float4 v4 = x0[i];
        const int e = i * 4;
        const int n = e / (LT * CT);
        const int rem = e - n * (LT * CT);
        const int m = rem / CT;
        const int k = rem % CT;
        const int mt = m / 128, mloc = m % 128;
        const int m16b = mloc >> 4, r16 = mloc & 15;
        const int kslab = k >> 3;
        const int slot = ((k & 4) >> 1) + ((r16 >> 3) & 1);
        const int tb = (r16 & 7) << 2;
        float* base = g_fa + ((((size_t)(n * NTIL + mt) * 32 + kslab) * 8 + m16b) << 7);
        float v[4] = {v4.x, v4.y, v4.z, v4.w};
#pragma unroll
        for (int j = 0; j < 4; j++)
            base[(tb + j) * 4 + slot] = to_tf32(v[j] * SQ);
    } else {
        const int ib = i - half;
        float4 v4 = x1[ib];
        const int e = ib * 4;
        const int n = e / (ST * CT);
        const int rem = e - n * (ST * CT);
        const int srow = rem / CT;
        const int k = rem % CT;
        const int nt = srow / 128, nloc = srow % 128;
        const int n8b = nloc >> 3, r8 = nloc & 7;
        const int kslab = k >> 3;
        const int slot = (k & 4) >> 2;
        const int tb = r8 << 2;
        float* base = g_fb + ((((size_t)(n * NTIL + nt) * 32 + kslab) * 16 + n8b) << 6);
        float v[4] = {v4.x, v4.y, v4.z, v4.w};
#pragma unroll
        for (int j = 0; j < 4; j++)
            base[(tb + j) * 2 + slot] = to_tf32(v[j] * SQ);
    }
}

// ---------------- K1: tf32 MMA GEMM, direct-fragment epilogue ----------------
#define KCHUNKS 8               // k32 chunks
#define STG_B 32768             // 16KB A + 16KB B per stage
#define DSMEM_B 65536           // 2 stages

extern __shared__ char dsm[];

__global__ __launch_bounds__(256, 2) void gemm_mma_kernel() {
    const int n = blockIdx.z;
    const int mt = blockIdx.y;
    const int nt = blockIdx.x;
    const int bm = mt * 128;
    const int bn = nt * 128;
    const int tid = threadIdx.x;
    const int wid = tid >> 5;
    const int lane = tid & 31;
    const uint32_t sb = smem_u32(dsm);

    const int wm = wid & 3;
    const int wn = wid >> 2;

    float acc[2][8][4];
#pragma unroll
    for (int mi = 0; mi < 2; mi++)
#pragma unroll
        for (int nj = 0; nj < 8; nj++)
#pragma unroll
            for (int q = 0; q < 4; q++) acc[mi][nj][q] = 0.0f;

    const float4* fa4 = (const float4*)g_fa + (size_t)(n * NTIL + mt) * 8192;
    const float4* fb4 = (const float4*)g_fb + (size_t)(n * NTIL + nt) * 8192;

    auto load_chunk = [&](int c, int s) {
        uint32_t dA = sb + s * STG_B + tid * 16;
        uint32_t dB = dA + 16384;
        const float4* pA = fa4 + c * 1024 + tid;
        const float4* pB = fb4 + c * 1024 + tid;
#pragma unroll
        for (int q = 0; q < 4; q++) {
            cpa16(dA + q * 4096, pA + q * 256);
            cpa16(dB + q * 4096, pB + q * 256);
        }
    };

    load_chunk(0, 0);
    CP_COMMIT();

    for (int c = 0; c < KCHUNKS; c++) {
        const int s = c & 1;
        if (c < KCHUNKS - 1) {
            load_chunk(c + 1, s ^ 1);
            CP_COMMIT();
            CP_WAIT1();
        } else {
            CP_WAIT0();
        }
        __syncthreads();

        const uint32_t sA = sb + s * STG_B;
        const uint32_t sB = sA + 16384;

#pragma unroll
        for (int s8 = 0; s8 < 4; s8++) {
            uint32_t a[2][4];
#pragma unroll
            for (int mi = 0; mi < 2; mi++)
                lds128(a[mi], sA + (uint32_t)(((s8 * 8 + wm * 2 + mi) << 9) + lane * 16));
#pragma unroll
            for (int nj = 0; nj < 8; nj++) {
                uint32_t b[2];
                lds64(b, sB + (uint32_t)(((s8 * 16 + wn * 8 + nj) << 8) + lane * 8));
                mma_tf32(acc[0][nj], a[0], b);
                mma_tf32(acc[1][nj], a[1], b);
            }
        }
        __syncthreads();
    }

    // ---- direct-fragment epilogue: E = exp(acc) -> STG.64 + register sums ----
    __shared__ float rowp[2][128];   // [wn][row]
    __shared__ float colp[4][128];   // [wm][col]

    float rs[2][2] = {{0.f, 0.f}, {0.f, 0.f}};   // [mi][qh]
    float cs[8][2];                              // [nj][b]
#pragma unroll
    for (int nj = 0; nj < 8; nj++) { cs[nj][0] = 0.f; cs[nj][1] = 0.f; }

    float* Cn = g_sim + (size_t)n * LT * ST;
    const int r0 = bm + wm * 32 + (lane >> 2);
    const int c0 = bn + wn * 64 + 2 * (lane & 3);
#pragma unroll
    for (int mi = 0; mi < 2; mi++) {
#pragma unroll
        for (int nj = 0; nj < 8; nj++) {
            float e0 = __expf(acc[mi][nj][0]);
            float e1 = __expf(acc[mi][nj][1]);
            float e2 = __expf(acc[mi][nj][2]);
            float e3 = __expf(acc[mi][nj][3]);
            size_t off = (size_t)(r0 + mi * 16) * ST + c0 + nj * 8;
            *(float2*)(Cn + off) = make_float2(e0, e1);
            *(float2*)(Cn + off + (size_t)8 * ST) = make_float2(e2, e3);
            rs[mi][0] += e0 + e1;
            rs[mi][1] += e2 + e3;
            cs[nj][0] += e0 + e2;
            cs[nj][1] += e1 + e3;
        }
    }

    // row partials: reduce over lane&3 (cols within warp)
#pragma unroll
    for (int mi = 0; mi < 2; mi++) {
#pragma unroll
        for (int qh = 0; qh < 2; qh++) {
            float v = rs[mi][qh];
            v += __shfl_xor_sync(0xffffffffu, v, 1);
            v += __shfl_xor_sync(0xffffffffu, v, 2);
            if ((lane & 3) == 0)
                rowp[wn][wm * 32 + mi * 16 + qh * 8 + (lane >> 2)] = v;
        }
    }
    // col partials: reduce over lane>>2 (rows within warp)
#pragma unroll
    for (int nj = 0; nj < 8; nj++) {
#pragma unroll
        for (int b = 0; b < 2; b++) {
            float v = cs[nj][b];
            v += __shfl_xor_sync(0xffffffffu, v, 4);
            v += __shfl_xor_sync(0xffffffffu, v, 8);
            v += __shfl_xor_sync(0xffffffffu, v, 16);
            if (lane < 4)
                colp[wm][wn * 64 + nj * 8 + 2 * lane + b] = v;
        }
    }
    __syncthreads();

    if (tid < 128) {
        g_prs[(size_t)(n * LT + bm + tid) * NTIL + nt] = rowp[0][tid] + rowp[1][tid];
    } else if (tid < 256) {
        int c = tid - 128;
        g_pcs[((size_t)n * NTIL + mt) * ST + bn + c] =
            colp[0][c] + colp[1][c] + colp[2][c] + colp[3][c];
    }
}

// ---------------- merged small reductions ----------------
__global__ __launch_bounds__(256) void sum_merge() {
    int i = blockIdx.x * 256 + threadIdx.x;
    if (i < NB * LT) {
        const float* p = g_prs + (size_t)i * NTIL;
        float s = 0.0f;
#pragma unroll 10
        for (int t = 0; t < NTIL; t++) s += p[t];
        g_rowinv[i] = 1.0f / s;
    } else if (i < NB * LT + NB * ST) {
        int k = i - NB * LT;
        int n = k / ST, s = k % ST;
        float sum = 0.0f;
#pragma unroll 10
        for (int t = 0; t < NTIL; t++) sum += g_pcs[((size_t)n * NTIL + t) * ST + s];
        g_colinv[k] = 1.0f / sum;
    }
}
__global__ __launch_bounds__(256) void max_merge() {
    int i = blockIdx.x * 256 + threadIdx.x;
    if (i < NB * LT) {
        const float* p = g_crp + (size_t)i * SBLK;
        float m = 0.0f;
#pragma unroll
        for (int t = 0; t < SBLK; t++) m = fmaxf(m, p[t]);
        g_crowmax[i] = m;
    } else if (i < NB * LT + NB * ST) {
        int k = i - NB * LT;
        int n = k / ST, s = k % ST;
        float m = 0.0f;
#pragma unroll 16
        for (int t = 0; t < LCH; t++) m = fmaxf(m, g_pcm[((size_t)(n * LCH + t)) * ST + s]);
        g_ccolmax[k] = m;
    }
}

// ---------------- conf pass: thread owns 8 cols (2 x float4), walks LPER rows ----------------
__global__ __launch_bounds__(256) void conf_kernel(float* __restrict__ out) {
    const int s0 = blockIdx.x * 2048 + threadIdx.x * 8;
    const int by = blockIdx.y, n = blockIdx.z;
    const int lane = threadIdx.x & 31, wid = threadIdx.x >> 5;
    const bool valid = (s0 < ST);

    __shared__ float ris[LPER];
    __shared__ float wmx[8][LPER];
    for (int i = threadIdx.x; i < LPER; i += 256)
        ris[i] = g_rowinv[n * LT + by * LPER + i];
    __syncthreads();

    float4 ci0 = make_float4(0.f, 0.f, 0.f, 0.f), ci1 = ci0;
    if (valid) {
        ci0 = *(const float4*)(g_colinv + n * ST + s0);
        ci1 = *(const float4*)(g_colinv + n * ST + s0 + 4);
    }

    const size_t base = (size_t)n * LT * ST + (size_t)(by * LPER) * ST + s0;
    const float* Eb = g_sim + base;
    float* Ob = out + base;

    float cm[8] = {0.f, 0.f, 0.f, 0.f, 0.f, 0.f, 0.f, 0.f};
    for (int i = 0; i < LPER; i++) {
        const float ri = ris[i];
        float w = 0.0f;
        if (valid) {
            float4 E0 = *(const float4*)(Eb + (size_t)i * ST);
            float4 E1 = *(const float4*)(Eb + (size_t)i * ST + 4);
            float4 c0, c1;
            c0.x = E0.x * E0.x * ri * ci0.x;
            c0.y = E0.y * E0.y * ri * ci0.y;
            c0.z = E0.z * E0.z * ri * ci0.z;
            c0.w = E0.w * E0.w * ri * ci0.w;
            c1.x = E1.x * E1.x * ri * ci1.x;
            c1.y = E1.y * E1.y * ri * ci1.y;
            c1.z = E1.z * E1.z * ri * ci1.z;
            c1.w = E1.w * E1.w * ri * ci1.w;
            *(float4*)(Ob + (size_t)i * ST) = c0;
            *(float4*)(Ob + (size_t)i * ST + 4) = c1;
            cm[0] = fmaxf(cm[0], c0.x); cm[1] = fmaxf(cm[1], c0.y);
            cm[2] = fmaxf(cm[2], c0.z); cm[3] = fmaxf(cm[3], c0.w);
            cm[4] = fmaxf(cm[4], c1.x); cm[5] = fmaxf(cm[5], c1.y);
            cm[6] = fmaxf(cm[6], c1.z); cm[7] = fmaxf(cm[7], c1.w);
            w = fmaxf(fmaxf(fmaxf(c0.x, c0.y), fmaxf(c0.z, c0.w)),
                      fmaxf(fmaxf(c1.x, c1.y), fmaxf(c1.z, c1.w)));
        }
#pragma unroll
        for (int o = 16; o > 0; o >>= 1) w = fmaxf(w, __shfl_xor_sync(0xffffffffu, w, o));
        if (lane == 0) wmx[wid][i] = w;
    }
    if (valid) {
        float* pm = g_pcm + ((size_t)(n * LCH + by)) * ST + s0;
        *(float4*)(pm)     = make_float4(cm[0], cm[1], cm[2], cm[3]);
        *(float4*)(pm + 4) = make_float4(cm[4], cm[5], cm[6], cm[7]);
    }
    __syncthreads();
    for (int i = threadIdx.x; i < LPER; i += 256) {
        float m = wmx[0][i];
#pragma unroll
        for (int w = 1; w < 8; w++) m = fmaxf(m, wmx[w][i]);
        g_crp[((size_t)n * LT + by * LPER + i) * SBLK + blockIdx.x] = m;
    }
}

// ---------------- zero-fill mask+scores regions ----------------
__global__ __launch_bounds__(256) void zero_kernel(float4* __restrict__ dst, unsigned n4) {
    unsigned i = blockIdx.x * 256u + threadIdx.x;
    if (i < n4) dst[i] = make_float4(0.f, 0.f, 0.f, 0.f);
}

// ---------------- scatter: one block per row; write sparse matches ----------------
__global__ __launch_bounds__(256) void scatter_kernel(float* __restrict__ out) {
    const int l = blockIdx.x;
    const int n = blockIdx.y;
    const float rm = g_crowmax[n * LT + l];
    if (!(rm > THRESH)) return;
    const int h0 = l / GW, w0 = l % GW;
    if (h0 < BORDER || h0 >= GW - BORDER || w0 < BORDER || w0 >= GW - BORDER) return;

    const float* crow = out + ((size_t)n * LT + l) * ST;
    float* mrow = out + (size_t)NB * LT * ST + ((size_t)n * LT + l) * ST;
    float* srow = out + 2 * (size_t)NB * LT * ST + ((size_t)n * LT + l) * ST;
    const float* ccm = g_ccolmax + n * ST;

    for (int s = threadIdx.x; s < ST; s += 256) {
        float c = crow[s];
        if (c == rm && c > THRESH && c == ccm[s]) {
            const int h1 = s / GW, w1 = s % GW;
            if (h1 >= BORDER && h1 < GW - BORDER && w1 >= BORDER && w1 < GW - BORDER) {
                mrow[s] = 1.0f;
                srow[s] = c;
            }
        }
    }
}

// ---------------- host ----------------
extern "C" void kernel_launch(void* const* d_in, const int* in_sizes, int n_in,
                              void* d_out, int out_size) {
    const float* x0 = (const float*)d_in[0];
    const float* x1 = (const float*)d_in[1];
    float* out = (float*)d_out;

    static int smem_set = 0;
    if (!smem_set) {
        cudaFuncSetAttribute(gemm_mma_kernel, cudaFuncAttributeMaxDynamicSharedMemorySize,
                             DSMEM_B);
        smem_set = 1;
    }

    const size_t tot = (size_t)NB * LT * ST;
    int write_ms = (out_size >= (long long)(3 * tot)) ? 1 : 0;

    prep_kernel<<<(2 * NB * LT * CT / 4) / 256, 256>>>((const float4*)x0, (const float4*)x1);

    gemm_mma_kernel<<<dim3(NTIL, NTIL, NB), 256, DSMEM_B>>>();

    sum_merge<<<(NB * (LT + ST) + 255) / 256, 256>>>();

    conf_kernel<<<dim3(SBLK, LCH, NB), 256>>>(out);

    max_merge<<<(NB * (LT + ST) + 255) / 256, 256>>>();

    if (write_ms) {
        const unsigned n4 = (unsigned)(2 * tot / 4);  // mask+scores as float4
        zero_kernel<<<(n4 + 255) / 256, 256>>>((float4*)(out + tot), n4);
        scatter_kernel<<<dim3(LT, NB), 256>>>(out);
    }
}

// round 15
// speedup vs baseline: 1.6699x; 1.1345x over previous
#include <cuda_runtime.h>
#include <cuda_fp16.h>
#include <math.h>
#include <stdint.h>

// Problem constants
#define NB 2
#define LT 6400
#define ST 6400
#define CT 256
#define GW 80
#define BORDER 2
#define SQ 0.19764235f   // sqrt(1/(256*0.1))
#define THRESH 0.2f
#define NTIL 50          // 6400/128 tiles per dim
#define LCH 64           // l-chunks in conf pass
#define LPER (LT / LCH)  // 100
#define SBLK 4           // s-blocks in conf pass (ceil(6400/2048))

// ---------------- scratch ----------------
__device__ float g_sim[(size_t)NB * LT * ST];          // stores E = exp(sim)
__device__ float g_rowinv[NB * LT];
__device__ float g_colinv[NB * ST];
__device__ float g_crowmax[NB * LT];
__device__ float g_ccolmax[NB * ST];
__device__ float g_prs[(size_t)NB * LT * NTIL];        // row partial sums of E
__device__ float g_pcs[(size_t)NB * NTIL * ST];        // col partial sums of E
__device__ float g_pcm[(size_t)NB * LCH * ST];         // conf col-max partials
__device__ float g_crp[(size_t)NB * LT * SBLK];        // conf row-max partials
// fp16 operands (single term), row-major rows of 256 halfs
__device__ uint4 g_h0[(size_t)NB * LT * CT / 8];
__device__ uint4 g_h1[(size_t)NB * ST * CT / 8];

// ---------------- helpers ----------------
__device__ __forceinline__ uint32_t smem_u32(const void* p) {
    uint32_t a;
    asm("{ .reg .u64 t; cvta.to.shared.u64 t, %1; cvt.u32.u64 %0, t; }" : "=r"(a) : "l"(p));
    return a;
}
__device__ __forceinline__ void cpa16(uint32_t dst, const void* src) {
    asm volatile("cp.async.cg.shared.global [%0], [%1], 16;" :: "r"(dst), "l"(src));
}
#define CP_COMMIT() asm volatile("cp.async.commit_group;")
#define CP_WAIT1()  asm volatile("cp.async.wait_group 1;")
#define CP_WAIT0()  asm volatile("cp.async.wait_group 0;")

__device__ __forceinline__ void ldsm_x4(uint32_t* r, uint32_t addr) {
    asm volatile("ldmatrix.sync.aligned.m8n8.x4.shared.b16 {%0,%1,%2,%3}, [%4];"
        : "=r"(r[0]), "=r"(r[1]), "=r"(r[2]), "=r"(r[3]) : "r"(addr));
}
__device__ __forceinline__ void ldsm_x2(uint32_t* r, uint32_t addr) {
    asm volatile("ldmatrix.sync.aligned.m8n8.x2.shared.b16 {%0,%1}, [%2];"
        : "=r"(r[0]), "=r"(r[1]) : "r"(addr));
}
__device__ __forceinline__ void mma16816(float* d, const uint32_t* a, const uint32_t* b) {
    asm volatile(
        "mma.sync.aligned.m16n8k16.row.col.f32.f16.f16.f32 "
        "{%0,%1,%2,%3}, {%4,%5,%6,%7}, {%8,%9}, {%0,%1,%2,%3};"
        : "+f"(d[0]), "+f"(d[1]), "+f"(d[2]), "+f"(d[3])
        : "r"(a[0]), "r"(a[1]), "r"(a[2]), "r"(a[3]), "r"(b[0]), "r"(b[1]));
}

// ---------------- K0: fp32 -> scaled fp16 (flush-to-zero below normal range) ----------------
__device__ __forceinline__ uint32_t packh2(float a, float b) {
    __half2 t = __floats2half2_rn(a, b);
    return *(uint32_t*)&t;
}
__global__ __launch_bounds__(256) void prep_kernel(const float4* __restrict__ x0,
                                                   const float4* __restrict__ x1) {
    const int i = blockIdx.x * 256 + threadIdx.x;
    const int half = NB * LT * CT / 4;
    float4 v4 = (i < half) ? x0[i] : x1[i - half];
    float v[4] = {v4.x * SQ, v4.y * SQ, v4.z * SQ, v4.w * SQ};
#pragma unroll
    for (int j = 0; j < 4; j++)
        if (fabsf(v[j]) < 6.2e-5f) v[j] = 0.0f;   // no subnormals reach the MMA
    uint2 hv = make_uint2(packh2(v[0], v[1]), packh2(v[2], v[3]));
    if (i < half) ((uint2*)g_h0)[i] = hv;
    else          ((uint2*)g_h1)[i - half] = hv;
}

// ---------------- K1: fp16 single-term HMMA GEMM, direct-fragment epilogue ----------------
#define KCHUNKS 8               // k32 chunks
#define ASTR 40                 // fp16 elems per smem row (80B, conflict-free ldmatrix)
#define TILE_B (128 * ASTR * 2) // 10240 bytes per operand tile
#define STG_B (2 * TILE_B)      // 20480 per stage (A, B)
#define DSMEM_B (2 * STG_B)     // 40960

extern __shared__ char dsm[];

__global__ __launch_bounds__(256, 2) void gemm_mma_kernel() {
    const int n = blockIdx.z;
    const int mt = blockIdx.y;
    const int nt = blockIdx.x;
    const int bm = mt * 128;
    const int bn = nt * 128;
    const int tid = threadIdx.x;
    const int wid = tid >> 5;
    const int lane = tid & 31;
    const uint32_t sb = smem_u32(dsm);

    const int wm = wid & 3;   // warp m block (32 rows)
    const int wn = wid >> 2;  // warp n block (64 cols)

    float acc[2][8][4];
#pragma unroll
    for (int mi = 0; mi < 2; mi++)
#pragma unroll
        for (int nj = 0; nj < 8; nj++)
#pragma unroll
            for (int q = 0; q < 4; q++) acc[mi][nj][q] = 0.0f;

    const int lrow = tid >> 1;          // 0..127
    const int lq0 = (tid & 1) * 2;      // 0 or 2 (two uint4 each)
    const size_t aoff = (size_t)(n * LT + bm + lrow) * 32;  // uint4 units/row
    const size_t boff = (size_t)(n * ST + bn + lrow) * 32;
    const uint32_t drow = (uint32_t)(lrow * (ASTR * 2));

    auto load_chunk = [&](int c, int s) {
        uint32_t base = sb + s * STG_B;
        const uint4* pA = g_h0 + aoff + c * 4 + lq0;
        const uint4* pB = g_h1 + boff + c * 4 + lq0;
#pragma unroll
        for (int q = 0; q < 2; q++) {
            uint32_t d = base + drow + (lq0 + q) * 16;
            cpa16(d, pA + q);
            cpa16(d + TILE_B, pB + q);
        }
    };

    load_chunk(0, 0);
    CP_COMMIT();

    for (int c = 0; c < KCHUNKS; c++) {
        const int s = c & 1;
        if (c < KCHUNKS - 1) {
            load_chunk(c + 1, s ^ 1);
            CP_COMMIT();
            CP_WAIT1();
        } else {
            CP_WAIT0();
        }
        __syncthreads();

        const uint32_t AH = sb + s * STG_B;
        const uint32_t BH = AH + TILE_B;

#pragma unroll
        for (int kk = 0; kk < 2; kk++) {
            const int k0 = kk * 16;
            const int rA = wm * 32 + ((lane >> 3) & 1) * 8 + (lane & 7);
            const int kA = k0 + (lane >> 4) * 8;
            uint32_t ah[2][4];
#pragma unroll
            for (int mi = 0; mi < 2; mi++)
                ldsm_x4(ah[mi], AH + (uint32_t)((rA + mi * 16) * (ASTR * 2) + kA * 2));
            const int l16 = lane & 15;
            const int rBo = (l16 & 7);
            const int kB = k0 + ((l16 >> 3) & 1) * 8;
#pragma unroll
            for (int nj = 0; nj < 8; nj++) {
                uint32_t bh[2];
                ldsm_x2(bh, BH + (uint32_t)((wn * 64 + nj * 8 + rBo) * (ASTR * 2) + kB * 2));
                mma16816(acc[0][nj], ah[0], bh);
                mma16816(acc[1][nj], ah[1], bh);
            }
        }
        __syncthreads();
    }

    // ---- direct-fragment epilogue: E = exp(acc) -> STG.64 + register sums ----
    __shared__ float rowp[2][128];   // [wn][row]
    __shared__ float colp[4][128];   // [wm][col]

    float rs[2][2] = {{0.f, 0.f}, {0.f, 0.f}};   // [mi][qh]
    float cs[8][2];                              // [nj][b]
#pragma unroll
    for (int nj = 0; nj < 8; nj++) { cs[nj][0] = 0.f; cs[nj][1] = 0.f; }

    float* Cn = g_sim + (size_t)n * LT * ST;
    const int r0 = bm + wm * 32 + (lane >> 2);
    const int c0 = bn + wn * 64 + 2 * (lane & 3);
#pragma unroll
    for (int mi = 0; mi < 2; mi++) {
#pragma unroll
        for (int nj = 0; nj < 8; nj++) {
            float e0 = __expf(acc[mi][nj][0]);
            float e1 = __expf(acc[mi][nj][1]);
            float e2 = __expf(acc[mi][nj][2]);
            float e3 = __expf(acc[mi][nj][3]);
            size_t off = (size_t)(r0 + mi * 16) * ST + c0 + nj * 8;
            *(float2*)(Cn + off) = make_float2(e0, e1);
            *(float2*)(Cn + off + (size_t)8 * ST) = make_float2(e2, e3);
            rs[mi][0] += e0 + e1;
            rs[mi][1] += e2 + e3;
            cs[nj][0] += e0 + e2;
            cs[nj][1] += e1 + e3;
        }
    }

#pragma unroll
    for (int mi = 0; mi < 2; mi++) {
#pragma unroll
        for (int qh = 0; qh < 2; qh++) {
            float v = rs[mi][qh];
            v += __shfl_xor_sync(0xffffffffu, v, 1);
            v += __shfl_xor_sync(0xffffffffu, v, 2);
            if ((lane & 3) == 0)
                rowp[wn][wm * 32 + mi * 16 + qh * 8 + (lane >> 2)] = v;
        }
    }
#pragma unroll
    for (int nj = 0; nj < 8; nj++) {
#pragma unroll
        for (int b = 0; b < 2; b++) {
            float v = cs[nj][b];
            v += __shfl_xor_sync(0xffffffffu, v, 4);
            v += __shfl_xor_sync(0xffffffffu, v, 8);
            v += __shfl_xor_sync(0xffffffffu, v, 16);
            if (lane < 4)
                colp[wm][wn * 64 + nj * 8 + 2 * lane + b] = v;
        }
    }
    __syncthreads();

    if (tid < 128) {
        g_prs[(size_t)(n * LT + bm + tid) * NTIL + nt] = rowp[0][tid] + rowp[1][tid];
    } else if (tid < 256) {
        int c = tid - 128;
        g_pcs[((size_t)n * NTIL + mt) * ST + bn + c] =
            colp[0][c] + colp[1][c] + colp[2][c] + colp[3][c];
    }
}

// ---------------- merged small reductions ----------------
__global__ __launch_bounds__(256) void sum_merge() {
    int i = blockIdx.x * 256 + threadIdx.x;
    if (i < NB * LT) {
        const float* p = g_prs + (size_t)i * NTIL;
        float s = 0.0f;
#pragma unroll 10
        for (int t = 0; t < NTIL; t++) s += p[t];
        g_rowinv[i] = 1.0f / s;
    } else if (i < NB * LT + NB * ST) {
        int k = i - NB * LT;
        int n = k / ST, s = k % ST;
        float sum = 0.0f;
#pragma unroll 10
        for (int t = 0; t < NTIL; t++) sum += g_pcs[((size_t)n * NTIL + t) * ST + s];
        g_colinv[k] = 1.0f / sum;
    }
}
__global__ __launch_bounds__(256) void max_merge() {
    int i = blockIdx.x * 256 + threadIdx.x;
    if (i < NB * LT) {
        const float* p = g_crp + (size_t)i * SBLK;
        float m = 0.0f;
#pragma unroll
        for (int t = 0; t < SBLK; t++) m = fmaxf(m, p[t]);
        g_crowmax[i] = m;
    } else if (i < NB * LT + NB * ST) {
        int k = i - NB * LT;
        int n = k / ST, s = k % ST;
        float m = 0.0f;
#pragma unroll 16
        for (int t = 0; t < LCH; t++) m = fmaxf(m, g_pcm[((size_t)(n * LCH + t)) * ST + s]);
        g_ccolmax[k] = m;
    }
}

// ---------------- conf pass: thread owns 8 cols (2 x float4), walks LPER rows ----------------
__global__ __launch_bounds__(256) void conf_kernel(float* __restrict__ out) {
    const int s0 = blockIdx.x * 2048 + threadIdx.x * 8;
    const int by = blockIdx.y, n = blockIdx.z;
    const int lane = threadIdx.x & 31, wid = threadIdx.x >> 5;
    const bool valid = (s0 < ST);

    __shared__ float ris[LPER];
    __shared__ float wmx[8][LPER];
    for (int i = threadIdx.x; i < LPER; i += 256)
        ris[i] = g_rowinv[n * LT + by * LPER + i];
    __syncthreads();

    float4 ci0 = make_float4(0.f, 0.f, 0.f, 0.f), ci1 = ci0;
    if (valid) {
        ci0 = *(const float4*)(g_colinv + n * ST + s0);
        ci1 = *(const float4*)(g_colinv + n * ST + s0 + 4);
    }

    const size_t base = (size_t)n * LT * ST + (size_t)(by * LPER) * ST + s0;
    const float* Eb = g_sim + base;
    float* Ob = out + base;

    float cm[8] = {0.f, 0.f, 0.f, 0.f, 0.f, 0.f, 0.f, 0.f};
    for (int i = 0; i < LPER; i++) {
        const float ri = ris[i];
        float w = 0.0f;
        if (valid) {
            float4 E0 = *(const float4*)(Eb + (size_t)i * ST);
            float4 E1 = *(const float4*)(Eb + (size_t)i * ST + 4);
            float4 c0, c1;
            c0.x = E0.x * E0.x * ri * ci0.x;
            c0.y = E0.y * E0.y * ri * ci0.y;
            c0.z = E0.z * E0.z * ri * ci0.z;
            c0.w = E0.w * E0.w * ri * ci0.w;
            c1.x = E1.x * E1.x * ri * ci1.x;
            c1.y = E1.y * E1.y * ri * ci1.y;
            c1.z = E1.z * E1.z * ri * ci1.z;
            c1.w = E1.w * E1.w * ri * ci1.w;
            *(float4*)(Ob + (size_t)i * ST) = c0;
            *(float4*)(Ob + (size_t)i * ST + 4) = c1;
            cm[0] = fmaxf(cm[0], c0.x); cm[1] = fmaxf(cm[1], c0.y);
            cm[2] = fmaxf(cm[2], c0.z); cm[3] = fmaxf(cm[3], c0.w);
            cm[4] = fmaxf(cm[4], c1.x); cm[5] = fmaxf(cm[5], c1.y);
            cm[6] = fmaxf(cm[6], c1.z); cm[7] = fmaxf(cm[7], c1.w);
            w = fmaxf(fmaxf(fmaxf(c0.x, c0.y), fmaxf(c0.z, c0.w)),
                      fmaxf(fmaxf(c1.x, c1.y), fmaxf(c1.z, c1.w)));
        }
#pragma unroll
        for (int o = 16; o > 0; o >>= 1) w = fmaxf(w, __shfl_xor_sync(0xffffffffu, w, o));
        if (lane == 0) wmx[wid][i] = w;
    }
    if (valid) {
        float* pm = g_pcm + ((size_t)(n * LCH + by)) * ST + s0;
        *(float4*)(pm)     = make_float4(cm[0], cm[1], cm[2], cm[3]);
        *(float4*)(pm + 4) = make_float4(cm[4], cm[5], cm[6], cm[7]);
    }
    __syncthreads();
    for (int i = threadIdx.x; i < LPER; i += 256) {
        float m = wmx[0][i];
#pragma unroll
        for (int w = 1; w < 8; w++) m = fmaxf(m, wmx[w][i]);
        g_crp[((size_t)n * LT + by * LPER + i) * SBLK + blockIdx.x] = m;
    }
}

// ---------------- zero-fill mask+scores regions ----------------
__global__ __launch_bounds__(256) void zero_kernel(float4* __restrict__ dst, unsigned n4) {
    unsigned i = blockIdx.x * 256u + threadIdx.x;
    if (i < n4) dst[i] = make_float4(0.f, 0.f, 0.f, 0.f);
}

// ---------------- scatter: one block per row; write sparse matches ----------------
__global__ __launch_bounds__(256) void scatter_kernel(float* __restrict__ out) {
    const int l = blockIdx.x;
    const int n = blockIdx.y;
    const float rm = g_crowmax[n * LT + l];
    if (!(rm > THRESH)) return;
    const int h0 = l / GW, w0 = l % GW;
    if (h0 < BORDER || h0 >= GW - BORDER || w0 < BORDER || w0 >= GW - BORDER) return;

    const float* crow = out + ((size_t)n * LT + l) * ST;
    float* mrow = out + (size_t)NB * LT * ST + ((size_t)n * LT + l) * ST;
    float* srow = out + 2 * (size_t)NB * LT * ST + ((size_t)n * LT + l) * ST;
    const float* ccm = g_ccolmax + n * ST;

    for (int s = threadIdx.x; s < ST; s += 256) {
        float c = crow[s];
        if (c == rm && c > THRESH && c == ccm[s]) {
            const int h1 = s / GW, w1 = s % GW;
            if (h1 >= BORDER && h1 < GW - BORDER && w1 >= BORDER && w1 < GW - BORDER) {
                mrow[s] = 1.0f;
                srow[s] = c;
            }
        }
    }
}

// ---------------- host ----------------
extern "C" void kernel_launch(void* const* d_in, const int* in_sizes, int n_in,
                              void* d_out, int out_size) {
    const float* x0 = (const float*)d_in[0];
    const float* x1 = (const float*)d_in[1];
    float* out = (float*)d_out;

    static int smem_set = 0;
    if (!smem_set) {
        cudaFuncSetAttribute(gemm_mma_kernel, cudaFuncAttributeMaxDynamicSharedMemorySize,
                             DSMEM_B);
        smem_set = 1;
    }

    const size_t tot = (size_t)NB * LT * ST;
    int write_ms = (out_size >= (long long)(3 * tot)) ? 1 : 0;

    prep_kernel<<<(2 * NB * LT * CT / 4) / 256, 256>>>((const float4*)x0, (const float4*)x1);

    gemm_mma_kernel<<<dim3(NTIL, NTIL, NB), 256, DSMEM_B>>>();

    sum_merge<<<(NB * (LT + ST) + 255) / 256, 256>>>();

    conf_kernel<<<dim3(SBLK, LCH, NB), 256>>>(out);

    max_merge<<<(NB * (LT + ST) + 255) / 256, 256>>>();

    if (write_ms) {
        const unsigned n4 = (unsigned)(2 * tot / 4);  // mask+scores as float4
        zero_kernel<<<(n4 + 255) / 256, 256>>>((float4*)(out + tot), n4);
        scatter_kernel<<<dim3(LT, NB), 256>>>(out);
    }
}